// round 4
// baseline (speedup 1.0000x reference)
#include <cuda_runtime.h>

// CRF loss, linear-domain scan. One CTA (128 threads) = TWO batch rows.
// Thread j holds column j of E=exp(trans) once (64 f32x2 regs) and computes
// alpha updates for both rows each step (interleaved -> 2 independent chains
// per warp). One __syncthreads per step covers both rows. Deferred
// power-of-2 renorm every 4 steps via redux.sync.max.s32 (values >= 0).

namespace {
constexpr int TT = 128;
constexpr int SS = 1024;
constexpr int NB = 256;
constexpr int START_TAG = 126;
constexpr int END_TAG = 127;
}

typedef unsigned long long ull;
__device__ double g_part[NB];

__device__ __forceinline__ ull pack2f(float lo, float hi) {
    ull r;
    asm("mov.b64 %0, {%1, %2};" : "=l"(r) : "f"(lo), "f"(hi));
    return r;
}

// Two interleaved dot products (rows A and B) against the shared E column.
__device__ __forceinline__ void dotrow2(const float* __restrict__ arA,
                                        const float* __restrict__ arB,
                                        const ull* __restrict__ E,
                                        float& dA, float& dB) {
    ull aA[4] = {0ull, 0ull, 0ull, 0ull};
    ull aB[4] = {0ull, 0ull, 0ull, 0ull};
    const double2* apA = reinterpret_cast<const double2*>(arA);
    const double2* apB = reinterpret_cast<const double2*>(arB);
#pragma unroll
    for (int k = 0; k < 16; k++) {
        double2 xa = apA[2 * k];
        double2 ya = apA[2 * k + 1];
        double2 xb = apB[2 * k];
        double2 yb = apB[2 * k + 1];
        ull xa0 = __double_as_longlong(xa.x), xa1 = __double_as_longlong(xa.y);
        ull ya0 = __double_as_longlong(ya.x), ya1 = __double_as_longlong(ya.y);
        ull xb0 = __double_as_longlong(xb.x), xb1 = __double_as_longlong(xb.y);
        ull yb0 = __double_as_longlong(yb.x), yb1 = __double_as_longlong(yb.y);
        asm("fma.rn.f32x2 %0, %1, %2, %0;" : "+l"(aA[0]) : "l"(xa0), "l"(E[4 * k + 0]));
        asm("fma.rn.f32x2 %0, %1, %2, %0;" : "+l"(aB[0]) : "l"(xb0), "l"(E[4 * k + 0]));
        asm("fma.rn.f32x2 %0, %1, %2, %0;" : "+l"(aA[1]) : "l"(xa1), "l"(E[4 * k + 1]));
        asm("fma.rn.f32x2 %0, %1, %2, %0;" : "+l"(aB[1]) : "l"(xb1), "l"(E[4 * k + 1]));
        asm("fma.rn.f32x2 %0, %1, %2, %0;" : "+l"(aA[2]) : "l"(ya0), "l"(E[4 * k + 2]));
        asm("fma.rn.f32x2 %0, %1, %2, %0;" : "+l"(aB[2]) : "l"(yb0), "l"(E[4 * k + 2]));
        asm("fma.rn.f32x2 %0, %1, %2, %0;" : "+l"(aA[3]) : "l"(ya1), "l"(E[4 * k + 3]));
        asm("fma.rn.f32x2 %0, %1, %2, %0;" : "+l"(aB[3]) : "l"(yb1), "l"(E[4 * k + 3]));
    }
    asm("add.rn.f32x2 %0, %0, %1;" : "+l"(aA[0]) : "l"(aA[1]));
    asm("add.rn.f32x2 %0, %0, %1;" : "+l"(aB[0]) : "l"(aB[1]));
    asm("add.rn.f32x2 %0, %0, %1;" : "+l"(aA[2]) : "l"(aA[3]));
    asm("add.rn.f32x2 %0, %0, %1;" : "+l"(aB[2]) : "l"(aB[3]));
    asm("add.rn.f32x2 %0, %0, %1;" : "+l"(aA[0]) : "l"(aA[2]));
    asm("add.rn.f32x2 %0, %0, %1;" : "+l"(aB[0]) : "l"(aB[2]));
    float loA, hiA, loB, hiB;
    asm("mov.b64 {%0, %1}, %2;" : "=f"(loA), "=f"(hiA) : "l"(aA[0]));
    asm("mov.b64 {%0, %1}, %2;" : "=f"(loB), "=f"(hiB) : "l"(aB[0]));
    dA = loA + hiA;
    dB = loB + hiB;
}

template <bool REN>
__device__ __forceinline__ void crf_step2(const float* __restrict__ arA,
                                          float* __restrict__ awA,
                                          const float* __restrict__ arB,
                                          float* __restrict__ awB,
                                          const ull* __restrict__ E,
                                          float eA, float eB, int j,
                                          float* redA, float* redB) {
    float dA, dB;
    dotrow2(arA, arB, E, dA, dB);
    float vA = dA * eA;
    float vB = dB * eB;
    awA[j] = vA;
    awB[j] = vB;
    if (REN) {
        int mA, mB;  // values >= 0: fp max == s32 max on bit patterns
        asm volatile("redux.sync.max.s32 %0, %1, 0xffffffff;"
                     : "=r"(mA) : "r"(__float_as_int(vA)));
        asm volatile("redux.sync.max.s32 %0, %1, 0xffffffff;"
                     : "=r"(mB) : "r"(__float_as_int(vB)));
        if ((j & 31) == 0) {
            redA[j >> 5] = __int_as_float(mA);
            redB[j >> 5] = __int_as_float(mB);
        }
    }
    __syncthreads();
}

__device__ __forceinline__ void consume_max(const float* red, int& le, float& sc) {
    float4 r4 = *reinterpret_cast<const float4*>(red);
    float mm = fmaxf(fmaxf(r4.x, r4.y), fmaxf(r4.z, r4.w));
    int ex = (__float_as_int(mm) >> 23) - 127;
    le += ex;
    sc = __int_as_float((127 - ex) << 23);
}

__global__ void __launch_bounds__(128, 1)
crf_scan_kernel(const float* __restrict__ em, const int* __restrict__ tags,
                const float* __restrict__ trans) {
    const int bA = 2 * blockIdx.x;
    const int bB = bA + 1;
    const int j = threadIdx.x;
    __shared__ __align__(16) float alphaA[2][TT];
    __shared__ __align__(16) float alphaB[2][TT];
    __shared__ __align__(16) float redA[4];
    __shared__ __align__(16) float redB[4];
    __shared__ __align__(16) float fin[16];

    const float* embA = em + (size_t)bA * SS * TT;
    const float* embB = em + (size_t)bB * SS * TT;
    const int* tgA = tags + bA * SS;
    const int* tgB = tags + bB * SS;

    // E column j in registers, packed (i, i+1) pairs.
    ull E[64];
#pragma unroll
    for (int k = 0; k < 64; k++) {
        float e0 = __expf(trans[(2 * k) * TT + j]);
        float e1 = __expf(trans[(2 * k + 1) * TT + j]);
        E[k] = pack2f(e0, e1);
    }

    // ---- gold path scores for both rows ----
    float goldA = 0.f, goldB = 0.f;
#pragma unroll
    for (int r = 0; r < SS / TT; r++) {
        int s = r * TT + j;
        int cA = tgA[s], cB = tgB[s];
        int pA = (s == 0) ? START_TAG : tgA[s - 1];
        int pB = (s == 0) ? START_TAG : tgB[s - 1];
        goldA += embA[s * TT + cA] + trans[pA * TT + cA];
        goldB += embB[s * TT + cB] + trans[pB * TT + cB];
    }
    if (j == 0) {
        goldA += trans[tgA[SS - 1] * TT + END_TAG];
        goldB += trans[tgB[SS - 1] * TT + END_TAG];
    }

    // one-time: max of the END transition row
    float tE = trans[END_TAG * TT + j];
    {
        float m = tE;
#pragma unroll
        for (int o = 16; o > 0; o >>= 1)
            m = fmaxf(m, __shfl_xor_sync(0xffffffffu, m, o));
        if ((j & 31) == 0) redA[j >> 5] = m;
    }
    __syncthreads();
    const float mTE = fmaxf(fmaxf(redA[0], redA[1]), fmaxf(redA[2], redA[3]));
    __syncthreads();
    if (j < 4) { redA[j] = 1.0f; redB[j] = 1.0f; }  // ex=0 for first group
    alphaA[0][j] = (j == START_TAG) ? 1.f : 0.f;
    alphaB[0][j] = (j == START_TAG) ? 1.f : 0.f;
    __syncthreads();

    // ---- scan, t = 1..1023 ----
    int leA = 0, leB = 0;
    float bA0 = embA[1 * TT + j], bA1 = embA[2 * TT + j];
    float bA2 = embA[3 * TT + j], bA3 = embA[4 * TT + j];
    float bB0 = embB[1 * TT + j], bB1 = embB[2 * TT + j];
    float bB2 = embB[3 * TT + j], bB3 = embB[4 * TT + j];
    float* a0A = alphaA[0]; float* a1A = alphaA[1];
    float* a0B = alphaB[0]; float* a1B = alphaB[1];

#pragma unroll 1
    for (int g = 0; g < 254; g++) {
        float scA, scB;
        consume_max(redA, leA, scA);
        consume_max(redB, leB, scB);
        float eA0 = __expf(bA0) * scA, eA1 = __expf(bA1);
        float eA2 = __expf(bA2),       eA3 = __expf(bA3);
        float eB0 = __expf(bB0) * scB, eB1 = __expf(bB1);
        float eB2 = __expf(bB2),       eB3 = __expf(bB3);
        const int tn = 4 * g + 5;
        float nA0 = embA[(tn + 0) * TT + j], nA1 = embA[(tn + 1) * TT + j];
        float nA2 = embA[(tn + 2) * TT + j], nA3 = embA[(tn + 3) * TT + j];
        float nB0 = embB[(tn + 0) * TT + j], nB1 = embB[(tn + 1) * TT + j];
        float nB2 = embB[(tn + 2) * TT + j], nB3 = embB[(tn + 3) * TT + j];
        crf_step2<false>(a0A, a1A, a0B, a1B, E, eA0, eB0, j, redA, redB);
        crf_step2<false>(a1A, a0A, a1B, a0B, E, eA1, eB1, j, redA, redB);
        crf_step2<false>(a0A, a1A, a0B, a1B, E, eA2, eB2, j, redA, redB);
        crf_step2<true >(a1A, a0A, a1B, a0B, E, eA3, eB3, j, redA, redB);
        bA0 = nA0; bA1 = nA1; bA2 = nA2; bA3 = nA3;
        bB0 = nB0; bB1 = nB1; bB2 = nB2; bB3 = nB3;
    }
    // group 255: t = 1017..1020, prefetch tail 1021..1023
    {
        float scA, scB;
        consume_max(redA, leA, scA);
        consume_max(redB, leB, scB);
        float eA0 = __expf(bA0) * scA, eA1 = __expf(bA1);
        float eA2 = __expf(bA2),       eA3 = __expf(bA3);
        float eB0 = __expf(bB0) * scB, eB1 = __expf(bB1);
        float eB2 = __expf(bB2),       eB3 = __expf(bB3);
        float nA0 = embA[1021 * TT + j], nA1 = embA[1022 * TT + j], nA2 = embA[1023 * TT + j];
        float nB0 = embB[1021 * TT + j], nB1 = embB[1022 * TT + j], nB2 = embB[1023 * TT + j];
        crf_step2<false>(a0A, a1A, a0B, a1B, E, eA0, eB0, j, redA, redB);
        crf_step2<false>(a1A, a0A, a1B, a0B, E, eA1, eB1, j, redA, redB);
        crf_step2<false>(a0A, a1A, a0B, a1B, E, eA2, eB2, j, redA, redB);
        crf_step2<true >(a1A, a0A, a1B, a0B, E, eA3, eB3, j, redA, redB);
        bA0 = nA0; bA1 = nA1; bA2 = nA2;
        bB0 = nB0; bB1 = nB1; bB2 = nB2;
    }
    // tail: t = 1021..1023 (final alpha ends in buffer 1)
    {
        float scA, scB;
        consume_max(redA, leA, scA);
        consume_max(redB, leB, scB);
        float eA0 = __expf(bA0) * scA, eA1 = __expf(bA1), eA2 = __expf(bA2);
        float eB0 = __expf(bB0) * scB, eB1 = __expf(bB1), eB2 = __expf(bB2);
        crf_step2<false>(a0A, a1A, a0B, a1B, E, eA0, eB0, j, redA, redB);
        crf_step2<false>(a1A, a0A, a1B, a0B, E, eA1, eB1, j, redA, redB);
        crf_step2<false>(a0A, a1A, a0B, a1B, E, eA2, eB2, j, redA, redB);
    }

    // ---- partitions + gold sums ----
    float eT = __expf(tE - mTE);
    float xA = a1A[j] * eT;
    float xB = a1B[j] * eT;
    float yA = goldA, yB = goldB;
#pragma unroll
    for (int o = 16; o > 0; o >>= 1) {
        xA += __shfl_xor_sync(0xffffffffu, xA, o);
        xB += __shfl_xor_sync(0xffffffffu, xB, o);
        yA += __shfl_xor_sync(0xffffffffu, yA, o);
        yB += __shfl_xor_sync(0xffffffffu, yB, o);
    }
    if ((j & 31) == 0) {
        int w = j >> 5;
        fin[w] = xA; fin[4 + w] = yA; fin[8 + w] = xB; fin[12 + w] = yB;
    }
    __syncthreads();
    if (j == 0) {
        float svA = fin[0] + fin[1] + fin[2] + fin[3];
        float sgA = fin[4] + fin[5] + fin[6] + fin[7];
        float svB = fin[8] + fin[9] + fin[10] + fin[11];
        float sgB = fin[12] + fin[13] + fin[14] + fin[15];
        const double LN2 = 0.6931471805599453;
        g_part[bA] = (double)leA * LN2 + (double)mTE + log((double)svA) - (double)sgA;
        g_part[bB] = (double)leB * LN2 + (double)mTE + log((double)svB) - (double)sgB;
    }
}

__global__ void crf_finish_kernel(float* __restrict__ out) {
    __shared__ double sd[NB];
    int t = threadIdx.x;
    sd[t] = g_part[t];
    __syncthreads();
#pragma unroll
    for (int o = NB / 2; o > 0; o >>= 1) {
        if (t < o) sd[t] += sd[t + o];
        __syncthreads();
    }
    if (t == 0) out[0] = (float)(sd[0] * (1.0 / NB));
}

extern "C" void kernel_launch(void* const* d_in, const int* in_sizes, int n_in,
                              void* d_out, int out_size) {
    const float* em = (const float*)d_in[0];     // [256,1024,128] f32
    const int* tags = (const int*)d_in[1];       // [256,1024] i32
    const float* trans = (const float*)d_in[2];  // [128,128] f32
    crf_scan_kernel<<<NB / 2, 128>>>(em, tags, trans);
    crf_finish_kernel<<<1, NB>>>((float*)d_out);
}

// round 5
// speedup vs baseline: 1.1747x; 1.1747x over previous
#include <cuda_runtime.h>

// CRF loss, linear-domain scan. One CTA (128 threads) per batch row, 2 CTAs/SM.
// Thread j owns column j of E=exp(trans) (64 f32x2 regs). Alpha ping-pongs in
// shared memory; one __syncthreads per step. Deferred power-of-2 renorm every
// 4 steps (redux.sync.max.s32 on non-negative floats). Final mean fused into
// the scan kernel via atomic ticket (last CTA reduces).

namespace {
constexpr int TT = 128;
constexpr int SS = 1024;
constexpr int NB = 256;
constexpr int START_TAG = 126;
constexpr int END_TAG = 127;
}

typedef unsigned long long ull;
__device__ double g_part[NB];
__device__ unsigned int g_ticket;

__device__ __forceinline__ ull pack2f(float lo, float hi) {
    ull r;
    asm("mov.b64 %0, {%1, %2};" : "=l"(r) : "f"(lo), "f"(hi));
    return r;
}

// dot of shared alpha[0..127] with this thread's E column; 4 accumulators.
__device__ __forceinline__ float dotrow(const float* __restrict__ ar,
                                        const ull* __restrict__ E) {
    ull acc[4] = {0ull, 0ull, 0ull, 0ull};
    const double2* ap = reinterpret_cast<const double2*>(ar);
#pragma unroll
    for (int k = 0; k < 16; k++) {
        double2 a = ap[2 * k];
        double2 b = ap[2 * k + 1];
        ull a0 = __double_as_longlong(a.x);
        ull a1 = __double_as_longlong(a.y);
        ull b0 = __double_as_longlong(b.x);
        ull b1 = __double_as_longlong(b.y);
        asm("fma.rn.f32x2 %0, %1, %2, %0;" : "+l"(acc[0]) : "l"(a0), "l"(E[4 * k + 0]));
        asm("fma.rn.f32x2 %0, %1, %2, %0;" : "+l"(acc[1]) : "l"(a1), "l"(E[4 * k + 1]));
        asm("fma.rn.f32x2 %0, %1, %2, %0;" : "+l"(acc[2]) : "l"(b0), "l"(E[4 * k + 2]));
        asm("fma.rn.f32x2 %0, %1, %2, %0;" : "+l"(acc[3]) : "l"(b1), "l"(E[4 * k + 3]));
    }
    asm("add.rn.f32x2 %0, %0, %1;" : "+l"(acc[0]) : "l"(acc[2]));
    asm("add.rn.f32x2 %0, %0, %1;" : "+l"(acc[1]) : "l"(acc[3]));
    asm("add.rn.f32x2 %0, %0, %1;" : "+l"(acc[0]) : "l"(acc[1]));
    float lo, hi;
    asm("mov.b64 {%0, %1}, %2;" : "=f"(lo), "=f"(hi) : "l"(acc[0]));
    return lo + hi;
}

template <bool REN>
__device__ __forceinline__ void crf_step(const float* __restrict__ ar,
                                         float* __restrict__ aw,
                                         const ull* __restrict__ E,
                                         float expem, int j, float* red) {
    float v = dotrow(ar, E) * expem;
    aw[j] = v;
    if (REN) {
        int m;  // v >= 0: fp max == s32 max on bit patterns
        asm volatile("redux.sync.max.s32 %0, %1, 0xffffffff;"
                     : "=r"(m) : "r"(__float_as_int(v)));
        if ((j & 31) == 0) red[j >> 5] = __int_as_float(m);
    }
    __syncthreads();
}

__device__ __forceinline__ void consume_max(const float* red, int& le, float& sc) {
    float4 r4 = *reinterpret_cast<const float4*>(red);
    float mm = fmaxf(fmaxf(r4.x, r4.y), fmaxf(r4.z, r4.w));
    int ex = (__float_as_int(mm) >> 23) - 127;
    le += ex;
    sc = __int_as_float((127 - ex) << 23);
}

__global__ void __launch_bounds__(128, 2)
crf_scan_kernel(const float* __restrict__ em, const int* __restrict__ tags,
                const float* __restrict__ trans, float* __restrict__ out) {
    const int b = blockIdx.x;
    const int j = threadIdx.x;
    __shared__ __align__(16) float alpha[2][TT];
    __shared__ __align__(16) float red[8];
    __shared__ int s_last;

    const float* emb = em + (size_t)b * SS * TT;
    const int* tg = tags + b * SS;

    // E column j in registers, packed (i, i+1) pairs.
    ull E[64];
#pragma unroll
    for (int k = 0; k < 64; k++) {
        float e0 = __expf(trans[(2 * k) * TT + j]);
        float e1 = __expf(trans[(2 * k + 1) * TT + j]);
        E[k] = pack2f(e0, e1);
    }

    // ---- gold path score ----
    float gold = 0.f;
#pragma unroll
    for (int r = 0; r < SS / TT; r++) {
        int s = r * TT + j;
        int cur = tg[s];
        int prev = (s == 0) ? START_TAG : tg[s - 1];
        gold += emb[s * TT + cur] + trans[prev * TT + cur];
    }
    if (j == 0) gold += trans[tg[SS - 1] * TT + END_TAG];

    // one-time: max of END transition row
    float tE = trans[END_TAG * TT + j];
    {
        float m = tE;
#pragma unroll
        for (int o = 16; o > 0; o >>= 1)
            m = fmaxf(m, __shfl_xor_sync(0xffffffffu, m, o));
        if ((j & 31) == 0) red[j >> 5] = m;
    }
    __syncthreads();
    const float mTE = fmaxf(fmaxf(red[0], red[1]), fmaxf(red[2], red[3]));
    __syncthreads();
    if (j < 4) red[j] = 1.0f;  // ex=0 for first group
    alpha[0][j] = (j == START_TAG) ? 1.f : 0.f;
    __syncthreads();

    // ---- phase skew: wave-2 CTAs (co-resident partner of bid-148) start
    // ~half a step later so LDS bursts interleave instead of convoying ----
    if (b >= 148) {
        float x = (float)j;
#pragma unroll 1
        for (int i = 0; i < 60; i++)
            asm volatile("add.f32 %0, %0, 1.0;" : "+f"(x));
        if (__float_as_int(x) == 0xdeadbeef) red[0] = x;  // keep alive, never true
    }

    // ---- scan, t = 1..1023 ----
    int le = 0;
    float b0 = emb[1 * TT + j];
    float b1 = emb[2 * TT + j];
    float b2 = emb[3 * TT + j];
    float b3 = emb[4 * TT + j];
    float* a0p = alpha[0];
    float* a1p = alpha[1];

#pragma unroll 1
    for (int g = 0; g < 254; g++) {
        float sc;
        consume_max(red, le, sc);
        float e0 = __expf(b0) * sc;
        float e1 = __expf(b1);
        float e2 = __expf(b2);
        float e3 = __expf(b3);
        const int tn = 4 * g + 5;
        float n0 = emb[(tn + 0) * TT + j];
        float n1 = emb[(tn + 1) * TT + j];
        float n2 = emb[(tn + 2) * TT + j];
        float n3 = emb[(tn + 3) * TT + j];
        crf_step<false>(a0p, a1p, E, e0, j, red);
        crf_step<false>(a1p, a0p, E, e1, j, red);
        crf_step<false>(a0p, a1p, E, e2, j, red);
        crf_step<true >(a1p, a0p, E, e3, j, red);
        b0 = n0; b1 = n1; b2 = n2; b3 = n3;
    }
    // group 255: t = 1017..1020, prefetch tail
    {
        float sc;
        consume_max(red, le, sc);
        float e0 = __expf(b0) * sc;
        float e1 = __expf(b1);
        float e2 = __expf(b2);
        float e3 = __expf(b3);
        float n0 = emb[1021 * TT + j];
        float n1 = emb[1022 * TT + j];
        float n2 = emb[1023 * TT + j];
        crf_step<false>(a0p, a1p, E, e0, j, red);
        crf_step<false>(a1p, a0p, E, e1, j, red);
        crf_step<false>(a0p, a1p, E, e2, j, red);
        crf_step<true >(a1p, a0p, E, e3, j, red);
        b0 = n0; b1 = n1; b2 = n2;
    }
    // tail: t = 1021..1023 (final alpha in buffer 1)
    {
        float sc;
        consume_max(red, le, sc);
        float e0 = __expf(b0) * sc;
        float e1 = __expf(b1);
        float e2 = __expf(b2);
        crf_step<false>(a0p, a1p, E, e0, j, red);
        crf_step<false>(a1p, a0p, E, e1, j, red);
        crf_step<false>(a0p, a1p, E, e2, j, red);
    }

    // ---- partition & gold reduction ----
    float v = a1p[j] * __expf(tE - mTE);
    float x = v, y = gold;
#pragma unroll
    for (int o = 16; o > 0; o >>= 1) {
        x += __shfl_xor_sync(0xffffffffu, x, o);
        y += __shfl_xor_sync(0xffffffffu, y, o);
    }
    if ((j & 31) == 0) { red[j >> 5] = x; red[4 + (j >> 5)] = y; }
    __syncthreads();
    if (j == 0) {
        float sumv = red[0] + red[1] + red[2] + red[3];
        float sumg = red[4] + red[5] + red[6] + red[7];
        double part = (double)le * 0.6931471805599453 + (double)mTE + log((double)sumv);
        g_part[b] = part - (double)sumg;
        __threadfence();
        unsigned int t = atomicAdd(&g_ticket, 1u);
        s_last = (t == NB - 1) ? 1 : 0;
    }
    __syncthreads();

    // ---- last CTA: reduce the 256 partials and write the mean ----
    if (s_last) {
        double d = __ldcg(&g_part[j]) + __ldcg(&g_part[j + 128]);
#pragma unroll
        for (int o = 16; o > 0; o >>= 1)
            d += __shfl_xor_sync(0xffffffffu, d, o);
        __shared__ double sd[4];
        if ((j & 31) == 0) sd[j >> 5] = d;
        __syncthreads();
        if (j == 0) {
            double tot = sd[0] + sd[1] + sd[2] + sd[3];
            out[0] = (float)(tot * (1.0 / NB));
            g_ticket = 0;  // reset for next launch/replay
        }
    }
}

extern "C" void kernel_launch(void* const* d_in, const int* in_sizes, int n_in,
                              void* d_out, int out_size) {
    const float* em = (const float*)d_in[0];     // [256,1024,128] f32
    const int* tags = (const int*)d_in[1];       // [256,1024] i32
    const float* trans = (const float*)d_in[2];  // [128,128] f32
    crf_scan_kernel<<<NB, 128>>>(em, tags, trans, (float*)d_out);
}